// round 1
// baseline (speedup 1.0000x reference)
#include <cuda_runtime.h>
#include <cuda_bf16.h>
#include <cstdint>

// ---------------------------------------------------------------------------
// BSplineKAN layer as one augmented GEMM:
//   A[n, i*8+j] = basis_j(clip(x[n,i]))  (j<7),  silu(clip(x[n,i]))  (j==7)
//   W[o, i*8+j] = coeff[o,i,j]           (j<7),  w_base[o,i]         (j==7)
//   out[n,o]    = sum_k A[n,k]*W[o,k] + bias[o]
// M=8192, N=1024, K=8192. TF32 tensor-core GEMM, fp32 accumulate.
// ---------------------------------------------------------------------------

#define M_DIM 8192
#define N_DIM 1024
#define D_IN  1024
#define K_DIM (D_IN * 8)   // 8192

// Scratch (static __device__ arrays: allowed; no allocation APIs used)
__device__ float g_Aaug[(size_t)M_DIM * K_DIM];   // 256 MB
__device__ float g_Waug[(size_t)N_DIM * K_DIM];   // 32 MB

// ---------------------------------------------------------------------------
// TF32 round helper (round-to-nearest-even into tf32, kept in a 32-bit reg)
// ---------------------------------------------------------------------------
__device__ __forceinline__ float to_tf32(float f) {
    unsigned r;
    asm("cvt.rna.tf32.f32 %0, %1;" : "=r"(r) : "f"(f));
    return __uint_as_float(r);
}

// ---------------------------------------------------------------------------
// Cubic B-spline basis, literal Cox-de Boor matching the reference exactly
// (incl. EPS-guarded repeated knots and the x==1 edge case where the
// reference produces an all-zero basis). All knot reciprocals are
// compile-time constants -> no fp divisions in the hot path.
// Grid: [-1,-1,-1,-1,-0.5,0,0.5,1,1,1,1]
// ---------------------------------------------------------------------------
__device__ __forceinline__ void bspline7(float x, float b[7]) {
    const float G[11] = {-1.f,-1.f,-1.f,-1.f,-0.5f,0.f,0.5f,1.f,1.f,1.f,1.f};

    // degree-0 indicators (intervals 0,1,2,7,8 are empty: repeated knots)
    float c0[10];
    c0[0] = 0.f; c0[1] = 0.f; c0[2] = 0.f;
    c0[3] = (x >= -1.0f && x < -0.5f) ? 1.f : 0.f;
    c0[4] = (x >= -0.5f && x <  0.0f) ? 1.f : 0.f;
    c0[5] = (x >=  0.0f && x <  0.5f) ? 1.f : 0.f;
    c0[6] = (x >=  0.5f && x <  1.0f) ? 1.f : 0.f;
    c0[7] = 0.f; c0[8] = 0.f;
    c0[9] = (x == 1.0f) ? 1.f : 0.f;   // right-closed last interval

    const float INV_EPS = 1e8f;        // 1/max(0,1e-8)
    const float H  = 2.0f;             // 1/0.5
    const float O  = 1.0f;             // 1/1.0
    const float T  = 0.66666669f;      // 1/1.5 (nearest float)

    // k = 1
    const float L1[9] = {INV_EPS,INV_EPS,INV_EPS,H,H,H,H,INV_EPS,INV_EPS};
    const float R1[9] = {INV_EPS,INV_EPS,H,H,H,H,INV_EPS,INV_EPS,INV_EPS};
    float c1[9];
#pragma unroll
    for (int t = 0; t < 9; t++)
        c1[t] = ((x - G[t]) * L1[t]) * c0[t] + ((G[t + 2] - x) * R1[t]) * c0[t + 1];

    // k = 2
    const float L2[8] = {INV_EPS,INV_EPS,H,O,O,O,H,INV_EPS};
    const float R2[8] = {INV_EPS,H,O,O,O,H,INV_EPS,INV_EPS};
    float c2[8];
#pragma unroll
    for (int t = 0; t < 8; t++)
        c2[t] = ((x - G[t]) * L2[t]) * c1[t] + ((G[t + 3] - x) * R2[t]) * c1[t + 1];

    // k = 3
    const float L3[7] = {INV_EPS,H,O,T,T,O,H};
    const float R3[7] = {H,O,T,T,O,H,INV_EPS};
#pragma unroll
    for (int t = 0; t < 7; t++)
        b[t] = ((x - G[t]) * L3[t]) * c2[t] + ((G[t + 4] - x) * R3[t]) * c2[t + 1];
}

// ---------------------------------------------------------------------------
// Pack kernels
// ---------------------------------------------------------------------------
__global__ void pack_a_kernel(const float* __restrict__ x) {
    int idx = blockIdx.x * blockDim.x + threadIdx.x;   // 0 .. 8M-1
    if (idx >= M_DIM * D_IN) return;
    float xv = x[idx];
    float xc = fminf(fmaxf(xv, -1.0f), 1.0f);

    float b[7];
    bspline7(xc, b);
    float s = xc / (1.0f + __expf(-xc));   // silu

    int n = idx >> 10;          // /1024
    int i = idx & 1023;
    float4* dst = reinterpret_cast<float4*>(&g_Aaug[(size_t)n * K_DIM + (size_t)i * 8]);
    float4 lo = make_float4(to_tf32(b[0]), to_tf32(b[1]), to_tf32(b[2]), to_tf32(b[3]));
    float4 hi = make_float4(to_tf32(b[4]), to_tf32(b[5]), to_tf32(b[6]), to_tf32(s));
    dst[0] = lo;
    dst[1] = hi;
}

__global__ void pack_w_kernel(const float* __restrict__ coeff,
                              const float* __restrict__ w_base) {
    int idx = blockIdx.x * blockDim.x + threadIdx.x;   // 0 .. 1M-1
    if (idx >= N_DIM * D_IN) return;
    int o = idx >> 10;
    int i = idx & 1023;
    const float* c = &coeff[(size_t)idx * 7];
    float4 lo = make_float4(to_tf32(c[0]), to_tf32(c[1]), to_tf32(c[2]), to_tf32(c[3]));
    float4 hi = make_float4(to_tf32(c[4]), to_tf32(c[5]), to_tf32(c[6]),
                            to_tf32(w_base[idx]));
    float4* dst = reinterpret_cast<float4*>(&g_Waug[(size_t)o * K_DIM + (size_t)i * 8]);
    dst[0] = lo;
    dst[1] = hi;
}

// ---------------------------------------------------------------------------
// TF32 GEMM: C[M,N] = A[M,K] * W[N,K]^T + bias
// 128x128 CTA tile, BK=16, double-buffered cp.async, warp grid 2(m) x 4(n),
// warp tile 64x32, mma.sync.m16n8k8.tf32.
// ---------------------------------------------------------------------------
#define BM 128
#define BN 128
#define BK 16
#define LDS_PAD 20   // stride in floats: (BK=16)+4 -> conflict-free frag loads

__device__ __forceinline__ void cp_async16(void* smem, const void* gmem) {
    unsigned saddr = (unsigned)__cvta_generic_to_shared(smem);
    asm volatile("cp.async.cg.shared.global [%0], [%1], 16;\n"
                 :: "r"(saddr), "l"(gmem));
}
#define CP_COMMIT() asm volatile("cp.async.commit_group;\n" ::: "memory")
#define CP_WAIT1()  asm volatile("cp.async.wait_group 1;\n" ::: "memory")

__device__ __forceinline__ void mma_tf32(float* d, const unsigned* a, const unsigned* b) {
    asm volatile(
        "mma.sync.aligned.m16n8k8.row.col.f32.tf32.tf32.f32 "
        "{%0,%1,%2,%3}, {%4,%5,%6,%7}, {%8,%9}, {%0,%1,%2,%3};"
        : "+f"(d[0]), "+f"(d[1]), "+f"(d[2]), "+f"(d[3])
        : "r"(a[0]), "r"(a[1]), "r"(a[2]), "r"(a[3]), "r"(b[0]), "r"(b[1]));
}

__global__ __launch_bounds__(256, 2)
void gemm_kernel(const float* __restrict__ bias, float* __restrict__ C) {
    __shared__ float sA[2][BM * LDS_PAD];
    __shared__ float sB[2][BN * LDS_PAD];

    const int tid  = threadIdx.x;
    const int bm   = blockIdx.y * BM;
    const int bn   = blockIdx.x * BN;
    const int warp = tid >> 5;
    const int lane = tid & 31;
    const int wm   = (warp & 1) * 64;   // 2 warps along M
    const int wn   = (warp >> 1) * 32;  // 4 warps along N
    const int g    = lane >> 2;         // groupID 0..7
    const int tg   = lane & 3;          // thread-in-group 0..3

    float acc[4][4][4];
#pragma unroll
    for (int mt = 0; mt < 4; mt++)
#pragma unroll
        for (int nt = 0; nt < 4; nt++)
#pragma unroll
            for (int r = 0; r < 4; r++) acc[mt][nt][r] = 0.f;

    // stage loader: 512 16B chunks per tile per matrix, 2 per thread
    auto load_stage = [&](int stage, int k0) {
#pragma unroll
        for (int i = 0; i < 2; i++) {
            int c   = tid + i * 256;
            int row = c >> 2;
            int kc  = c & 3;
            cp_async16(&sA[stage][row * LDS_PAD + kc * 4],
                       &g_Aaug[(size_t)(bm + row) * K_DIM + k0 + kc * 4]);
        }
#pragma unroll
        for (int i = 0; i < 2; i++) {
            int c   = tid + i * 256;
            int row = c >> 2;
            int kc  = c & 3;
            cp_async16(&sB[stage][row * LDS_PAD + kc * 4],
                       &g_Waug[(size_t)(bn + row) * K_DIM + k0 + kc * 4]);
        }
    };

    load_stage(0, 0);
    CP_COMMIT();

    const int nK = K_DIM / BK;   // 512
    for (int kt = 0; kt < nK; kt++) {
        if (kt + 1 < nK) load_stage((kt + 1) & 1, (kt + 1) * BK);
        CP_COMMIT();
        CP_WAIT1();
        __syncthreads();

        const float* A = sA[kt & 1];
        const float* B = sB[kt & 1];

#pragma unroll
        for (int ks = 0; ks < 2; ks++) {
            const int k = ks * 8;
            unsigned af[4][4];
            unsigned bf[4][2];
#pragma unroll
            for (int mt = 0; mt < 4; mt++) {
                int m = wm + mt * 16;
                af[mt][0] = __float_as_uint(A[(m + g)     * LDS_PAD + k + tg]);
                af[mt][1] = __float_as_uint(A[(m + g + 8) * LDS_PAD + k + tg]);
                af[mt][2] = __float_as_uint(A[(m + g)     * LDS_PAD + k + tg + 4]);
                af[mt][3] = __float_as_uint(A[(m + g + 8) * LDS_PAD + k + tg + 4]);
            }
#pragma unroll
            for (int nt = 0; nt < 4; nt++) {
                int n = wn + nt * 8;
                bf[nt][0] = __float_as_uint(B[(n + g) * LDS_PAD + k + tg]);
                bf[nt][1] = __float_as_uint(B[(n + g) * LDS_PAD + k + tg + 4]);
            }
#pragma unroll
            for (int mt = 0; mt < 4; mt++)
#pragma unroll
                for (int nt = 0; nt < 4; nt++)
                    mma_tf32(acc[mt][nt], af[mt], bf[nt]);
        }
        __syncthreads();
    }

    // epilogue: add bias, store
#pragma unroll
    for (int mt = 0; mt < 4; mt++) {
#pragma unroll
        for (int nt = 0; nt < 4; nt++) {
            int m0 = bm + wm + mt * 16 + g;
            int n0 = bn + wn + nt * 8 + tg * 2;
            float bs0 = __ldg(&bias[n0]);
            float bs1 = __ldg(&bias[n0 + 1]);
            float2 v0 = make_float2(acc[mt][nt][0] + bs0, acc[mt][nt][1] + bs1);
            float2 v1 = make_float2(acc[mt][nt][2] + bs0, acc[mt][nt][3] + bs1);
            *reinterpret_cast<float2*>(&C[(size_t)m0 * N_DIM + n0]) = v0;
            *reinterpret_cast<float2*>(&C[(size_t)(m0 + 8) * N_DIM + n0]) = v1;
        }
    }
}

// ---------------------------------------------------------------------------
// Launch
// ---------------------------------------------------------------------------
extern "C" void kernel_launch(void* const* d_in, const int* in_sizes, int n_in,
                              void* d_out, int out_size) {
    const float* x      = (const float*)d_in[0];  // (8192, 1024)
    const float* coeff  = (const float*)d_in[1];  // (1024, 1024, 7)
    const float* w_base = (const float*)d_in[2];  // (1024, 1024)
    const float* bias   = (const float*)d_in[3];  // (1024,)
    float* out = (float*)d_out;                   // (8192, 1024)

    pack_a_kernel<<<(M_DIM * D_IN) / 256, 256>>>(x);
    pack_w_kernel<<<(N_DIM * D_IN) / 256, 256>>>(coeff, w_base);
    gemm_kernel<<<dim3(N_DIM / BN, M_DIM / BM), 256>>>(bias, out);
}

// round 4
// speedup vs baseline: 2.4152x; 2.4152x over previous
#include <cuda_runtime.h>
#include <cuda_fp16.h>
#include <cstdint>

// ---------------------------------------------------------------------------
// BSplineKAN as one augmented fp16 GEMM (fp32 accumulate) on mma.sync:
//   A[n, i*8+j] = basis_j(clip(x[n,i]))  (j<7),  silu(clip(x[n,i]))  (j==7)
//   W[o, i*8+j] = coeff[o,i,j]           (j<7),  w_base[o,i]         (j==7)
//   out = A (8192x8192) @ W^T (1024x8192) + bias
// fp16 mantissa == tf32 mantissa (11 bits) -> same accuracy, half the bytes,
// double the FLOP per mma instruction (m16n8k16 vs m16n8k8).
// ---------------------------------------------------------------------------

#define M_DIM 8192
#define N_DIM 1024
#define D_IN  1024
#define K_DIM (D_IN * 8)      // 8192 (fp16 elements)

#define BM 128
#define BN 256
#define BK 64                 // fp16 per stage-row = 128 bytes
#define STAGES 3
#define NK (K_DIM / BK)       // 128 k-iterations

// gmem tile images (dense 128B rows, pair-permuted within each 16-elem block)
#define A_TILE_BYTES (BM * 128)   // 16384
#define B_TILE_BYTES (BN * 128)   // 32768

// smem: rows padded to 40 granules (4B each) = 160B for conflict-free LDS.64
#define ROW_GRAN 40
#define A_STAGE_BYTES (BM * ROW_GRAN * 4)   // 20480
#define B_STAGE_BYTES (BN * ROW_GRAN * 4)   // 40960
#define STAGE_BYTES (A_STAGE_BYTES + B_STAGE_BYTES)
#define DYN_BYTES (STAGES * STAGE_BYTES)    // 184320

__device__ __align__(128) unsigned char g_Aaug[(size_t)M_DIM * K_DIM * 2];  // 128MB
__device__ __align__(128) unsigned char g_Waug[(size_t)N_DIM * K_DIM * 2];  // 16MB

// ---------------------------------------------------------------------------
// Cubic B-spline basis, literal Cox-de Boor matching the reference exactly
// (EPS-guarded repeated knots; x==1 edge yields all-zero basis as in ref).
// Grid: [-1,-1,-1,-1,-0.5,0,0.5,1,1,1,1]; all reciprocals compile-time.
// ---------------------------------------------------------------------------
__device__ __forceinline__ void bspline7(float x, float b[7]) {
    const float G[11] = {-1.f,-1.f,-1.f,-1.f,-0.5f,0.f,0.5f,1.f,1.f,1.f,1.f};
    float c0[10];
    c0[0] = 0.f; c0[1] = 0.f; c0[2] = 0.f;
    c0[3] = (x >= -1.0f && x < -0.5f) ? 1.f : 0.f;
    c0[4] = (x >= -0.5f && x <  0.0f) ? 1.f : 0.f;
    c0[5] = (x >=  0.0f && x <  0.5f) ? 1.f : 0.f;
    c0[6] = (x >=  0.5f && x <  1.0f) ? 1.f : 0.f;
    c0[7] = 0.f; c0[8] = 0.f;
    c0[9] = (x == 1.0f) ? 1.f : 0.f;

    const float INV_EPS = 1e8f;
    const float H = 2.0f, O = 1.0f, T = 0.66666669f;

    const float L1[9] = {INV_EPS,INV_EPS,INV_EPS,H,H,H,H,INV_EPS,INV_EPS};
    const float R1[9] = {INV_EPS,INV_EPS,H,H,H,H,INV_EPS,INV_EPS,INV_EPS};
    float c1[9];
#pragma unroll
    for (int t = 0; t < 9; t++)
        c1[t] = ((x - G[t]) * L1[t]) * c0[t] + ((G[t + 2] - x) * R1[t]) * c0[t + 1];

    const float L2[8] = {INV_EPS,INV_EPS,H,O,O,O,H,INV_EPS};
    const float R2[8] = {INV_EPS,H,O,O,O,H,INV_EPS,INV_EPS};
    float c2[8];
#pragma unroll
    for (int t = 0; t < 8; t++)
        c2[t] = ((x - G[t]) * L2[t]) * c1[t] + ((G[t + 3] - x) * R2[t]) * c1[t + 1];

    const float L3[7] = {INV_EPS,H,O,T,T,O,H};
    const float R3[7] = {H,O,T,T,O,H,INV_EPS};
#pragma unroll
    for (int t = 0; t < 7; t++)
        b[t] = ((x - G[t]) * L3[t]) * c2[t] + ((G[t + 4] - x) * R3[t]) * c2[t + 1];
}

__device__ __forceinline__ unsigned h2(float a, float b) {
    __half2 h = __floats2half2_rn(a, b);
    return *reinterpret_cast<unsigned*>(&h);
}

// ---------------------------------------------------------------------------
// Pack kernels. Each thread handles one (row, even/odd dim pair) -> writes one
// 32B block (one k16 sub-block) as two uint4.
// Block granule layout (4B granules): [e01, o01, e23, o23, e45, o45, e67, o67]
// so a fragment LDS.64 at granule 2*tg yields k-pairs (tg, tg+4): exactly the
// {lo-k8, hi-k8} halves an m16n8k16 fragment wants.
// ---------------------------------------------------------------------------
__global__ void pack_a_kernel(const float* __restrict__ x) {
    int idx = blockIdx.x * blockDim.x + threadIdx.x;   // (n, ipair)
    if (idx >= M_DIM * (D_IN / 2)) return;
    int n  = idx >> 9;
    int ip = idx & 511;
    int i0 = ip * 2;

    float2 xv = *reinterpret_cast<const float2*>(&x[(size_t)n * D_IN + i0]);
    float xe = fminf(fmaxf(xv.x, -1.0f), 1.0f);
    float xo = fminf(fmaxf(xv.y, -1.0f), 1.0f);
    float be[7], bo[7];
    bspline7(xe, be);
    bspline7(xo, bo);
    float se = xe / (1.0f + __expf(-xe));
    float so = xo / (1.0f + __expf(-xo));

    int mt = n >> 7, r = n & 127;
    int kt = i0 >> 3;               // 8 dims per 64-elem stage row
    int blk = (i0 >> 1) & 3;        // k16 block within row
    unsigned char* base = g_Aaug
        + ((size_t)(mt * NK + kt) * A_TILE_BYTES) + (size_t)r * 128 + blk * 32;

    uint4 v0, v1;
    v0.x = h2(be[0], be[1]); v0.y = h2(bo[0], bo[1]);
    v0.z = h2(be[2], be[3]); v0.w = h2(bo[2], bo[3]);
    v1.x = h2(be[4], be[5]); v1.y = h2(bo[4], bo[5]);
    v1.z = h2(be[6], se);    v1.w = h2(bo[6], so);
    *reinterpret_cast<uint4*>(base)      = v0;
    *reinterpret_cast<uint4*>(base + 16) = v1;
}

__global__ void pack_w_kernel(const float* __restrict__ coeff,
                              const float* __restrict__ w_base) {
    int idx = blockIdx.x * blockDim.x + threadIdx.x;   // (o, ipair)
    if (idx >= N_DIM * (D_IN / 2)) return;
    int o  = idx >> 9;
    int ip = idx & 511;
    int i0 = ip * 2;

    const float* ce = &coeff[((size_t)o * D_IN + i0) * 7];
    const float* co = ce + 7;
    float we = w_base[(size_t)o * D_IN + i0];
    float wo = w_base[(size_t)o * D_IN + i0 + 1];

    int nt = o >> 8, r = o & 255;
    int kt = i0 >> 3;
    int blk = (i0 >> 1) & 3;
    unsigned char* base = g_Waug
        + ((size_t)(nt * NK + kt) * B_TILE_BYTES) + (size_t)r * 128 + blk * 32;

    uint4 v0, v1;
    v0.x = h2(ce[0], ce[1]); v0.y = h2(co[0], co[1]);
    v0.z = h2(ce[2], ce[3]); v0.w = h2(co[2], co[3]);
    v1.x = h2(ce[4], ce[5]); v1.y = h2(co[4], co[5]);
    v1.z = h2(ce[6], we);    v1.w = h2(co[6], wo);
    *reinterpret_cast<uint4*>(base)      = v0;
    *reinterpret_cast<uint4*>(base + 16) = v1;
}

// ---------------------------------------------------------------------------
// GEMM: 128x256 CTA tile, BK=64, 3-stage cp.async, 256 threads,
// 8 warps (2m x 4n), warp tile 64x64, mma.m16n8k16.f16.f32.
// ---------------------------------------------------------------------------
__device__ __forceinline__ void cp_async16(void* smem, const void* gmem) {
    unsigned saddr = (unsigned)__cvta_generic_to_shared(smem);
    asm volatile("cp.async.cg.shared.global [%0], [%1], 16;\n"
                 :: "r"(saddr), "l"(gmem));
}
#define CP_COMMIT() asm volatile("cp.async.commit_group;\n" ::: "memory")
#define CP_WAIT1()  asm volatile("cp.async.wait_group 1;\n" ::: "memory")

__device__ __forceinline__ void mma_f16(float* d, const unsigned* a, const unsigned* b) {
    asm volatile(
        "mma.sync.aligned.m16n8k16.row.col.f32.f16.f16.f32 "
        "{%0,%1,%2,%3}, {%4,%5,%6,%7}, {%8,%9}, {%0,%1,%2,%3};"
        : "+f"(d[0]), "+f"(d[1]), "+f"(d[2]), "+f"(d[3])
        : "r"(a[0]), "r"(a[1]), "r"(a[2]), "r"(a[3]), "r"(b[0]), "r"(b[1]));
}

__global__ __launch_bounds__(256, 1)
void gemm_kernel(const float* __restrict__ bias, float* __restrict__ C) {
    extern __shared__ __align__(16) unsigned char dyn[];
    unsigned* sm = reinterpret_cast<unsigned*>(dyn);  // granule-indexed

    const int tid  = threadIdx.x;
    const int warp = tid >> 5;
    const int lane = tid & 31;
    const int bm   = blockIdx.y * BM;
    const int bn   = blockIdx.x * BN;
    const int wm   = (warp >> 2) * 64;   // 2 warps along M
    const int wn   = (warp & 3) * 64;    // 4 warps along N
    const int g    = lane >> 2;
    const int tg   = lane & 3;

    const unsigned char* gA = g_Aaug + (size_t)blockIdx.y * NK * A_TILE_BYTES;
    const unsigned char* gB = g_Waug + (size_t)blockIdx.x * NK * B_TILE_BYTES;

    float acc[4][8][4];
#pragma unroll
    for (int mt = 0; mt < 4; mt++)
#pragma unroll
        for (int nt = 0; nt < 8; nt++)
#pragma unroll
            for (int r = 0; r < 4; r++) acc[mt][nt][r] = 0.f;

    // stage granule bases
    auto a_base = [&](int s) { return s * (STAGE_BYTES / 4); };
    auto b_base = [&](int s) { return s * (STAGE_BYTES / 4) + A_STAGE_BYTES / 4; };

    auto load_stage = [&](int s, int kt) {
        unsigned aoff = a_base(s);
        unsigned boff = b_base(s);
        const unsigned char* At = gA + (size_t)kt * A_TILE_BYTES;
        const unsigned char* Bt = gB + (size_t)kt * B_TILE_BYTES;
#pragma unroll
        for (int i = 0; i < 4; i++) {           // A: 1024 chunks
            int c = tid + i * 256;
            int row = c >> 3, seg = c & 7;
            cp_async16(&sm[aoff + row * ROW_GRAN + seg * 4], At + c * 16);
        }
#pragma unroll
        for (int i = 0; i < 8; i++) {           // B: 2048 chunks
            int c = tid + i * 256;
            int row = c >> 3, seg = c & 7;
            cp_async16(&sm[boff + row * ROW_GRAN + seg * 4], Bt + c * 16);
        }
    };

    load_stage(0, 0); CP_COMMIT();
    load_stage(1, 1); CP_COMMIT();

    for (int kt = 0; kt < NK; kt++) {
        const int s = kt % STAGES;
        CP_WAIT1();
        __syncthreads();
        if (kt + 2 < NK) load_stage((kt + 2) % STAGES, kt + 2);
        CP_COMMIT();

        const unsigned* A = &sm[a_base(s)];
        const unsigned* B = &sm[b_base(s)];

#pragma unroll
        for (int ks = 0; ks < 4; ks++) {        // 4 x k16
            const int gb = ks * 8 + 2 * tg;     // granule within row
            unsigned af[4][4];
            unsigned bf[8][2];
#pragma unroll
            for (int mt = 0; mt < 4; mt++) {
                int m = wm + mt * 16;
                uint2 lo = *reinterpret_cast<const uint2*>(&A[(m + g) * ROW_GRAN + gb]);
                uint2 hi = *reinterpret_cast<const uint2*>(&A[(m + g + 8) * ROW_GRAN + gb]);
                af[mt][0] = lo.x; af[mt][1] = hi.x; af[mt][2] = lo.y; af[mt][3] = hi.y;
            }
#pragma unroll
            for (int nt = 0; nt < 8; nt++) {
                int n = wn + nt * 8;
                uint2 v = *reinterpret_cast<const uint2*>(&B[(n + g) * ROW_GRAN + gb]);
                bf[nt][0] = v.x; bf[nt][1] = v.y;
            }
#pragma unroll
            for (int mt = 0; mt < 4; mt++)
#pragma unroll
                for (int nt = 0; nt < 8; nt++)
                    mma_f16(acc[mt][nt], af[mt], bf[nt]);
        }
        __syncthreads();
    }

    // epilogue
#pragma unroll
    for (int mt = 0; mt < 4; mt++) {
#pragma unroll
        for (int nt = 0; nt < 8; nt++) {
            int m0 = bm + wm + mt * 16 + g;
            int n0 = bn + wn + nt * 8 + tg * 2;
            float bs0 = __ldg(&bias[n0]);
            float bs1 = __ldg(&bias[n0 + 1]);
            float2 v0 = make_float2(acc[mt][nt][0] + bs0, acc[mt][nt][1] + bs1);
            float2 v1 = make_float2(acc[mt][nt][2] + bs0, acc[mt][nt][3] + bs1);
            *reinterpret_cast<float2*>(&C[(size_t)m0 * N_DIM + n0]) = v0;
            *reinterpret_cast<float2*>(&C[(size_t)(m0 + 8) * N_DIM + n0]) = v1;
        }
    }
}

// ---------------------------------------------------------------------------
// Launch
// ---------------------------------------------------------------------------
extern "C" void kernel_launch(void* const* d_in, const int* in_sizes, int n_in,
                              void* d_out, int out_size) {
    const float* x      = (const float*)d_in[0];
    const float* coeff  = (const float*)d_in[1];
    const float* w_base = (const float*)d_in[2];
    const float* bias   = (const float*)d_in[3];
    float* out = (float*)d_out;

    static bool attr_done = false;
    if (!attr_done) {
        cudaFuncSetAttribute(gemm_kernel,
                             cudaFuncAttributeMaxDynamicSharedMemorySize, DYN_BYTES);
        attr_done = true;
    }

    pack_a_kernel<<<(M_DIM * D_IN / 2) / 256, 256>>>(x);
    pack_w_kernel<<<(N_DIM * D_IN / 2) / 256, 256>>>(coeff, w_base);
    gemm_kernel<<<dim3(N_DIM / BN, M_DIM / BM), 256, DYN_BYTES>>>(bias, out);
}

// round 5
// speedup vs baseline: 2.9603x; 1.2257x over previous
#include <cuda_runtime.h>
#include <cuda_fp16.h>
#include <cstdint>

// ---------------------------------------------------------------------------
// BSplineKAN as one augmented fp16 GEMM (fp32 accumulate) on mma.sync:
//   A[n, i*8+j] = basis_j(clip(x[n,i]))  (j<7),  silu(clip(x[n,i]))  (j==7)
//   W[o, i*8+j] = coeff[o,i,j]           (j<7),  w_base[o,i]         (j==7)
//   out = A (8192x8192) @ W^T (1024x8192) + bias
// Pack kernels write SW128-swizzled K-major tile images; GEMM fragments load
// via ldmatrix.m8n8.x4 (conflict-free).
// ---------------------------------------------------------------------------

#define M_DIM 8192
#define N_DIM 1024
#define D_IN  1024
#define K_DIM (D_IN * 8)      // 8192 fp16 elements

#define BM 128
#define BN 256
#define BK 64                 // 64 fp16 = 128B row
#define STAGES 4
#define NK (K_DIM / BK)       // 128

#define A_TILE_BYTES (BM * 128)   // 16384
#define B_TILE_BYTES (BN * 128)   // 32768
#define STAGE_BYTES  (A_TILE_BYTES + B_TILE_BYTES)  // 49152
#define DYN_BYTES    (STAGES * STAGE_BYTES)         // 196608

__device__ __align__(128) unsigned char g_Aaug[(size_t)M_DIM * K_DIM * 2];  // 128MB
__device__ __align__(128) unsigned char g_Waug[(size_t)N_DIM * K_DIM * 2];  // 16MB

// ---------------------------------------------------------------------------
// Cubic B-spline basis, literal Cox-de Boor matching the reference exactly
// (EPS-guarded repeated knots; x==1 edge yields all-zero basis as in ref).
// Grid: [-1,-1,-1,-1,-0.5,0,0.5,1,1,1,1]; all reciprocals compile-time.
// ---------------------------------------------------------------------------
__device__ __forceinline__ void bspline7(float x, float b[7]) {
    const float G[11] = {-1.f,-1.f,-1.f,-1.f,-0.5f,0.f,0.5f,1.f,1.f,1.f,1.f};
    float c0[10];
    c0[0] = 0.f; c0[1] = 0.f; c0[2] = 0.f;
    c0[3] = (x >= -1.0f && x < -0.5f) ? 1.f : 0.f;
    c0[4] = (x >= -0.5f && x <  0.0f) ? 1.f : 0.f;
    c0[5] = (x >=  0.0f && x <  0.5f) ? 1.f : 0.f;
    c0[6] = (x >=  0.5f && x <  1.0f) ? 1.f : 0.f;
    c0[7] = 0.f; c0[8] = 0.f;
    c0[9] = (x == 1.0f) ? 1.f : 0.f;

    const float INV_EPS = 1e8f;
    const float H = 2.0f, O = 1.0f, T = 0.66666669f;

    const float L1[9] = {INV_EPS,INV_EPS,INV_EPS,H,H,H,H,INV_EPS,INV_EPS};
    const float R1[9] = {INV_EPS,INV_EPS,H,H,H,H,INV_EPS,INV_EPS,INV_EPS};
    float c1[9];
#pragma unroll
    for (int t = 0; t < 9; t++)
        c1[t] = ((x - G[t]) * L1[t]) * c0[t] + ((G[t + 2] - x) * R1[t]) * c0[t + 1];

    const float L2[8] = {INV_EPS,INV_EPS,H,O,O,O,H,INV_EPS};
    const float R2[8] = {INV_EPS,H,O,O,O,H,INV_EPS,INV_EPS};
    float c2[8];
#pragma unroll
    for (int t = 0; t < 8; t++)
        c2[t] = ((x - G[t]) * L2[t]) * c1[t] + ((G[t + 3] - x) * R2[t]) * c1[t + 1];

    const float L3[7] = {INV_EPS,H,O,T,T,O,H};
    const float R3[7] = {H,O,T,T,O,H,INV_EPS};
#pragma unroll
    for (int t = 0; t < 7; t++)
        b[t] = ((x - G[t]) * L3[t]) * c2[t] + ((G[t + 4] - x) * R3[t]) * c2[t + 1];
}

__device__ __forceinline__ unsigned h2(float a, float b) {
    __half2 h = __floats2half2_rn(a, b);
    return *reinterpret_cast<unsigned*>(&h);
}

// ---------------------------------------------------------------------------
// Pack kernels: K-major fp16 rows (128B), SW128 swizzle u ^ ((r&7)<<4).
// Dim i occupies the 16B atom (i&7) of its row: [b0..b6, silu] in k-order.
// Each thread packs a dim pair -> two adjacent atoms.
// ---------------------------------------------------------------------------
__global__ void pack_a_kernel(const float* __restrict__ x) {
    int idx = blockIdx.x * blockDim.x + threadIdx.x;   // (n, ipair)
    if (idx >= M_DIM * (D_IN / 2)) return;
    int n  = idx >> 9;
    int i0 = (idx & 511) * 2;

    float2 xv = *reinterpret_cast<const float2*>(&x[(size_t)n * D_IN + i0]);
    float xe = fminf(fmaxf(xv.x, -1.0f), 1.0f);
    float xo = fminf(fmaxf(xv.y, -1.0f), 1.0f);
    float be[7], bo[7];
    bspline7(xe, be);
    bspline7(xo, bo);
    float se = xe / (1.0f + __expf(-xe));
    float so = xo / (1.0f + __expf(-xo));

    int mt = n >> 7, r = n & 127;
    int kt = i0 >> 3;
    uint32_t u0 = ((uint32_t)r << 7) + ((uint32_t)(i0 & 7) << 4);
    uint32_t X  = ((uint32_t)(r & 7)) << 4;
    unsigned char* base = g_Aaug + (size_t)(mt * NK + kt) * A_TILE_BYTES;

    uint4 v0 = make_uint4(h2(be[0], be[1]), h2(be[2], be[3]),
                          h2(be[4], be[5]), h2(be[6], se));
    uint4 v1 = make_uint4(h2(bo[0], bo[1]), h2(bo[2], bo[3]),
                          h2(bo[4], bo[5]), h2(bo[6], so));
    *reinterpret_cast<uint4*>(base + (u0 ^ X))        = v0;
    *reinterpret_cast<uint4*>(base + ((u0 + 16) ^ X)) = v1;
}

__global__ void pack_w_kernel(const float* __restrict__ coeff,
                              const float* __restrict__ w_base) {
    int idx = blockIdx.x * blockDim.x + threadIdx.x;   // (o, ipair)
    if (idx >= N_DIM * (D_IN / 2)) return;
    int o  = idx >> 9;
    int i0 = (idx & 511) * 2;

    const float* ce = &coeff[((size_t)o * D_IN + i0) * 7];
    const float* co = ce + 7;
    float we = w_base[(size_t)o * D_IN + i0];
    float wo = w_base[(size_t)o * D_IN + i0 + 1];

    int nt = o >> 8, r = o & 255;
    int kt = i0 >> 3;
    uint32_t u0 = ((uint32_t)r << 7) + ((uint32_t)(i0 & 7) << 4);
    uint32_t X  = ((uint32_t)(r & 7)) << 4;
    unsigned char* base = g_Waug + (size_t)(nt * NK + kt) * B_TILE_BYTES;

    uint4 v0 = make_uint4(h2(ce[0], ce[1]), h2(ce[2], ce[3]),
                          h2(ce[4], ce[5]), h2(ce[6], we));
    uint4 v1 = make_uint4(h2(co[0], co[1]), h2(co[2], co[3]),
                          h2(co[4], co[5]), h2(co[6], wo));
    *reinterpret_cast<uint4*>(base + (u0 ^ X))        = v0;
    *reinterpret_cast<uint4*>(base + ((u0 + 16) ^ X)) = v1;
}

// ---------------------------------------------------------------------------
// GEMM: 128x256 CTA tile, BK=64, 4-stage cp.async, 256 threads,
// 8 warps (2m x 4n), warp tile 64x64, ldmatrix.x4 + mma.m16n8k16.f16.f32.
// ---------------------------------------------------------------------------
__device__ __forceinline__ void cp_async16(uint32_t saddr, const void* gmem) {
    asm volatile("cp.async.cg.shared.global [%0], [%1], 16;\n"
                 :: "r"(saddr), "l"(gmem));
}
#define CP_COMMIT() asm volatile("cp.async.commit_group;\n" ::: "memory")
#define CP_WAIT2()  asm volatile("cp.async.wait_group 2;\n" ::: "memory")

__device__ __forceinline__ void ldsm_x4(unsigned& r0, unsigned& r1,
                                        unsigned& r2, unsigned& r3, uint32_t a) {
    asm volatile("ldmatrix.sync.aligned.m8n8.x4.shared.b16 {%0,%1,%2,%3}, [%4];"
                 : "=r"(r0), "=r"(r1), "=r"(r2), "=r"(r3) : "r"(a));
}

__device__ __forceinline__ void mma_f16(float* d, const unsigned* a, const unsigned* b) {
    asm volatile(
        "mma.sync.aligned.m16n8k16.row.col.f32.f16.f16.f32 "
        "{%0,%1,%2,%3}, {%4,%5,%6,%7}, {%8,%9}, {%0,%1,%2,%3};"
        : "+f"(d[0]), "+f"(d[1]), "+f"(d[2]), "+f"(d[3])
        : "r"(a[0]), "r"(a[1]), "r"(a[2]), "r"(a[3]), "r"(b[0]), "r"(b[1]));
}

__global__ __launch_bounds__(256, 1)
void gemm_kernel(const float* __restrict__ bias, float* __restrict__ C) {
    extern __shared__ __align__(128) unsigned char dyn[];

    const int tid  = threadIdx.x;
    const int warp = tid >> 5;
    const int lane = tid & 31;
    const int bm   = blockIdx.y * BM;
    const int bn   = blockIdx.x * BN;
    const int wm   = (warp >> 2) * 64;   // 2 warps along M
    const int wn   = (warp & 3) * 64;    // 4 warps along N
    const int g    = lane >> 2;
    const int tg   = lane & 3;
    const int q    = lane >> 3;          // ldmatrix quad id
    const int li   = lane & 7;           // row within quad

    const uint32_t smem0 = (uint32_t)__cvta_generic_to_shared(dyn);

    const unsigned char* gA = g_Aaug + (size_t)blockIdx.y * NK * A_TILE_BYTES;
    const unsigned char* gB = g_Waug + (size_t)blockIdx.x * NK * B_TILE_BYTES;

    // ldmatrix per-lane geometry
    // A frag (mt): mat0 rows m..m+7 @k, mat1 rows m+8..15 @k, mat2/mat3 same @k+8
    const int rowA = wm + (q & 1) * 8 + li;
    const uint32_t colA = (uint32_t)((q >> 1) * 16);
    const uint32_t XA = (uint32_t)((rowA & 7) << 4);
    // B frag pair (nt,nt+1): mat0 rows n..n+7 @k, mat1 rows n..n+7 @k+8,
    //                        mat2 rows n+8..15 @k, mat3 rows n+8..15 @k+8
    const int rowB = wn + (q >> 1) * 8 + li;
    const uint32_t colB = (uint32_t)((q & 1) * 16);
    const uint32_t XB = (uint32_t)((rowB & 7) << 4);

    float acc[4][8][4];
#pragma unroll
    for (int mt = 0; mt < 4; mt++)
#pragma unroll
        for (int nt = 0; nt < 8; nt++)
#pragma unroll
            for (int r = 0; r < 4; r++) acc[mt][nt][r] = 0.f;

    auto load_stage = [&](int s, int kt) {
        uint32_t As = smem0 + s * STAGE_BYTES;
        uint32_t Bs = As + A_TILE_BYTES;
        const unsigned char* At = gA + (size_t)kt * A_TILE_BYTES;
        const unsigned char* Bt = gB + (size_t)kt * B_TILE_BYTES;
#pragma unroll
        for (int i = 0; i < 4; i++) {          // A: 1024 x 16B
            int c = tid + i * 256;
            cp_async16(As + c * 16, At + c * 16);
        }
#pragma unroll
        for (int i = 0; i < 8; i++) {          // B: 2048 x 16B
            int c = tid + i * 256;
            cp_async16(Bs + c * 16, Bt + c * 16);
        }
    };

    load_stage(0, 0); CP_COMMIT();
    load_stage(1, 1); CP_COMMIT();
    load_stage(2, 2); CP_COMMIT();

    for (int kt = 0; kt < NK; kt++) {
        const int s = kt & (STAGES - 1);
        CP_WAIT2();
        __syncthreads();

        const uint32_t As = smem0 + s * STAGE_BYTES;
        const uint32_t Bs = As + A_TILE_BYTES;

#pragma unroll
        for (int ks = 0; ks < 4; ks++) {
            const uint32_t kb = (uint32_t)(ks * 32);
            unsigned af[4][4];
            unsigned bf[8][2];
#pragma unroll
            for (int mt = 0; mt < 4; mt++)
                ldsm_x4(af[mt][0], af[mt][1], af[mt][2], af[mt][3],
                        As + (uint32_t)((rowA + mt * 16) << 7) + ((kb + colA) ^ XA));
#pragma unroll
            for (int np = 0; np < 4; np++)
                ldsm_x4(bf[np * 2][0], bf[np * 2][1], bf[np * 2 + 1][0], bf[np * 2 + 1][1],
                        Bs + (uint32_t)((rowB + np * 16) << 7) + ((kb + colB) ^ XB));
#pragma unroll
            for (int mt = 0; mt < 4; mt++)
#pragma unroll
                for (int nt = 0; nt < 8; nt++)
                    mma_f16(acc[mt][nt], af[mt], bf[nt]);
        }

        if (kt + 3 < NK) load_stage((kt + 3) & (STAGES - 1), kt + 3);
        CP_COMMIT();
    }

    // epilogue
#pragma unroll
    for (int mt = 0; mt < 4; mt++) {
#pragma unroll
        for (int nt = 0; nt < 8; nt++) {
            int m0 = bm + wm + mt * 16 + g;
            int n0 = bn + wn + nt * 8 + tg * 2;
            float bs0 = __ldg(&bias[n0]);
            float bs1 = __ldg(&bias[n0 + 1]);
            float2 v0 = make_float2(acc[mt][nt][0] + bs0, acc[mt][nt][1] + bs1);
            float2 v1 = make_float2(acc[mt][nt][2] + bs0, acc[mt][nt][3] + bs1);
            *reinterpret_cast<float2*>(&C[(size_t)m0 * N_DIM + n0]) = v0;
            *reinterpret_cast<float2*>(&C[(size_t)(m0 + 8) * N_DIM + n0]) = v1;
        }
    }
}

// ---------------------------------------------------------------------------
// Launch
// ---------------------------------------------------------------------------
extern "C" void kernel_launch(void* const* d_in, const int* in_sizes, int n_in,
                              void* d_out, int out_size) {
    const float* x      = (const float*)d_in[0];
    const float* coeff  = (const float*)d_in[1];
    const float* w_base = (const float*)d_in[2];
    const float* bias   = (const float*)d_in[3];
    float* out = (float*)d_out;

    cudaFuncSetAttribute(gemm_kernel,
                         cudaFuncAttributeMaxDynamicSharedMemorySize, DYN_BYTES);

    pack_a_kernel<<<(M_DIM * D_IN / 2) / 256, 256>>>(x);
    pack_w_kernel<<<(N_DIM * D_IN / 2) / 256, 256>>>(coeff, w_base);
    gemm_kernel<<<dim3(N_DIM / BN, M_DIM / BM), 256, DYN_BYTES>>>(bias, out);
}

// round 7
// speedup vs baseline: 2.9736x; 1.0045x over previous
#include <cuda_runtime.h>
#include <cuda_fp16.h>
#include <cstdint>

// ---------------------------------------------------------------------------
// BSplineKAN as one augmented fp16 GEMM (fp32 accumulate) on mma.sync:
//   A[n, i*8+j] = basis_j(clip(x[n,i]))  (j<7),  silu(clip(x[n,i]))  (j==7)
//   W[o, i*8+j] = coeff[o,i,j]           (j<7),  w_base[o,i]         (j==7)
//   out = A (8192x8192) @ W^T (1024x8192) + bias
// SW128-swizzled K-major tile images in gmem; ldmatrix.x4 fragment loads;
// 128x128 CTA tile, 2 CTAs/SM to hide barrier/epilogue stalls.
// ---------------------------------------------------------------------------

#define M_DIM 8192
#define N_DIM 1024
#define D_IN  1024
#define K_DIM (D_IN * 8)      // 8192 fp16 elements

#define BM 128
#define BN 128
#define BK 64                 // 64 fp16 = 128B row
#define STAGES 3
#define NK (K_DIM / BK)       // 128

#define A_TILE_BYTES (BM * 128)   // 16384
#define B_TILE_BYTES (BN * 128)   // 16384
#define STAGE_BYTES  (A_TILE_BYTES + B_TILE_BYTES)  // 32768
#define DYN_BYTES    (STAGES * STAGE_BYTES)         // 98304 (x2 CTAs = 192KB/SM)

__device__ __align__(128) unsigned char g_Aaug[(size_t)M_DIM * K_DIM * 2];  // 128MB
__device__ __align__(128) unsigned char g_Waug[(size_t)N_DIM * K_DIM * 2];  // 16MB

// ---------------------------------------------------------------------------
// Cubic B-spline basis, literal Cox-de Boor matching the reference exactly
// (EPS-guarded repeated knots; x==1 edge yields all-zero basis as in ref).
// Grid: [-1,-1,-1,-1,-0.5,0,0.5,1,1,1,1]; all reciprocals compile-time.
// ---------------------------------------------------------------------------
__device__ __forceinline__ void bspline7(float x, float b[7]) {
    const float G[11] = {-1.f,-1.f,-1.f,-1.f,-0.5f,0.f,0.5f,1.f,1.f,1.f,1.f};
    float c0[10];
    c0[0] = 0.f; c0[1] = 0.f; c0[2] = 0.f;
    c0[3] = (x >= -1.0f && x < -0.5f) ? 1.f : 0.f;
    c0[4] = (x >= -0.5f && x <  0.0f) ? 1.f : 0.f;
    c0[5] = (x >=  0.0f && x <  0.5f) ? 1.f : 0.f;
    c0[6] = (x >=  0.5f && x <  1.0f) ? 1.f : 0.f;
    c0[7] = 0.f; c0[8] = 0.f;
    c0[9] = (x == 1.0f) ? 1.f : 0.f;

    const float INV_EPS = 1e8f;
    const float H = 2.0f, O = 1.0f, T = 0.66666669f;

    const float L1[9] = {INV_EPS,INV_EPS,INV_EPS,H,H,H,H,INV_EPS,INV_EPS};
    const float R1[9] = {INV_EPS,INV_EPS,H,H,H,H,INV_EPS,INV_EPS,INV_EPS};
    float c1[9];
#pragma unroll
    for (int t = 0; t < 9; t++)
        c1[t] = ((x - G[t]) * L1[t]) * c0[t] + ((G[t + 2] - x) * R1[t]) * c0[t + 1];

    const float L2[8] = {INV_EPS,INV_EPS,H,O,O,O,H,INV_EPS};
    const float R2[8] = {INV_EPS,H,O,O,O,H,INV_EPS,INV_EPS};
    float c2[8];
#pragma unroll
    for (int t = 0; t < 8; t++)
        c2[t] = ((x - G[t]) * L2[t]) * c1[t] + ((G[t + 3] - x) * R2[t]) * c1[t + 1];

    const float L3[7] = {INV_EPS,H,O,T,T,O,H};
    const float R3[7] = {H,O,T,T,O,H,INV_EPS};
#pragma unroll
    for (int t = 0; t < 7; t++)
        b[t] = ((x - G[t]) * L3[t]) * c2[t] + ((G[t + 4] - x) * R3[t]) * c2[t + 1];
}

__device__ __forceinline__ unsigned h2(float a, float b) {
    __half2 h = __floats2half2_rn(a, b);
    return *reinterpret_cast<unsigned*>(&h);
}

// ---------------------------------------------------------------------------
// Fused pack kernel. Blocks [0, PACK_A_BLOCKS) pack A (4 dims/thread);
// remaining blocks pack W (4 rows-of-7 per thread).
// Image: K-major fp16 rows (128B), SW128 swizzle u ^ ((r&7)<<4); dim i is the
// 16B atom (i&7) of row r in tile (mt|nt, kt): [b0..b6, silu/w_base] k-order.
// ---------------------------------------------------------------------------
#define PACK_A_BLOCKS ((M_DIM * D_IN / 4) / 256)    // 8192
#define PACK_W_BLOCKS ((N_DIM * D_IN / 4) / 256)    // 1024

__global__ void pack_kernel(const float* __restrict__ x,
                            const float* __restrict__ coeff,
                            const float* __restrict__ w_base) {
    if (blockIdx.x < PACK_A_BLOCKS) {
        int idx = blockIdx.x * blockDim.x + threadIdx.x;   // (n, iquad)
        int n  = idx >> 8;
        int i0 = (idx & 255) * 4;

        float4 xv = *reinterpret_cast<const float4*>(&x[(size_t)n * D_IN + i0]);
        float xc[4] = {fminf(fmaxf(xv.x, -1.f), 1.f), fminf(fmaxf(xv.y, -1.f), 1.f),
                       fminf(fmaxf(xv.z, -1.f), 1.f), fminf(fmaxf(xv.w, -1.f), 1.f)};

        int mt = n >> 7, r = n & 127;
        int kt = i0 >> 3;
        uint32_t u0 = ((uint32_t)r << 7) + ((uint32_t)(i0 & 7) << 4);
        uint32_t X  = ((uint32_t)(r & 7)) << 4;
        unsigned char* base = g_Aaug + (size_t)(mt * NK + kt) * A_TILE_BYTES;

#pragma unroll
        for (int d = 0; d < 4; d++) {
            float b[7];
            bspline7(xc[d], b);
            float s = xc[d] / (1.0f + __expf(-xc[d]));
            uint4 v = make_uint4(h2(b[0], b[1]), h2(b[2], b[3]),
                                 h2(b[4], b[5]), h2(b[6], s));
            *reinterpret_cast<uint4*>(base + ((u0 + d * 16) ^ X)) = v;
        }
    } else {
        int idx = (blockIdx.x - PACK_A_BLOCKS) * blockDim.x + threadIdx.x;
        int o  = idx >> 8;
        int i0 = (idx & 255) * 4;

        int nt = o >> 7, r = o & 127;
        int kt = i0 >> 3;
        uint32_t u0 = ((uint32_t)r << 7) + ((uint32_t)(i0 & 7) << 4);
        uint32_t X  = ((uint32_t)(r & 7)) << 4;
        unsigned char* base = g_Waug + (size_t)(nt * NK + kt) * B_TILE_BYTES;

        const float* cbase = &coeff[((size_t)o * D_IN + i0) * 7];
        const float* wbase = &w_base[(size_t)o * D_IN + i0];
#pragma unroll
        for (int d = 0; d < 4; d++) {
            const float* c = cbase + d * 7;
            uint4 v = make_uint4(h2(c[0], c[1]), h2(c[2], c[3]),
                                 h2(c[4], c[5]), h2(c[6], wbase[d]));
            *reinterpret_cast<uint4*>(base + ((u0 + d * 16) ^ X)) = v;
        }
    }
}

// ---------------------------------------------------------------------------
// GEMM: 128x128 CTA tile, BK=64, 3-stage cp.async, 256 threads, 2 CTAs/SM,
// 8 warps (2m x 4n), warp tile 64x32, ldmatrix.x4 + mma.m16n8k16.f16.f32.
// ---------------------------------------------------------------------------
__device__ __forceinline__ void cp_async16(uint32_t saddr, const void* gmem) {
    asm volatile("cp.async.cg.shared.global [%0], [%1], 16;\n"
                 :: "r"(saddr), "l"(gmem));
}
#define CP_COMMIT() asm volatile("cp.async.commit_group;\n" ::: "memory")
#define CP_WAIT1()  asm volatile("cp.async.wait_group 1;\n" ::: "memory")

__device__ __forceinline__ void ldsm_x4(unsigned& r0, unsigned& r1,
                                        unsigned& r2, unsigned& r3, uint32_t a) {
    asm volatile("ldmatrix.sync.aligned.m8n8.x4.shared.b16 {%0,%1,%2,%3}, [%4];"
                 : "=r"(r0), "=r"(r1), "=r"(r2), "=r"(r3) : "r"(a));
}

__device__ __forceinline__ void mma_f16(float* d, const unsigned* a, const unsigned* b) {
    asm volatile(
        "mma.sync.aligned.m16n8k16.row.col.f32.f16.f16.f32 "
        "{%0,%1,%2,%3}, {%4,%5,%6,%7}, {%8,%9}, {%0,%1,%2,%3};"
        : "+f"(d[0]), "+f"(d[1]), "+f"(d[2]), "+f"(d[3])
        : "r"(a[0]), "r"(a[1]), "r"(a[2]), "r"(a[3]), "r"(b[0]), "r"(b[1]));
}

__global__ __launch_bounds__(256, 2)
void gemm_kernel(const float* __restrict__ bias, float* __restrict__ C) {
    extern __shared__ __align__(128) unsigned char dyn[];

    const int tid  = threadIdx.x;
    const int warp = tid >> 5;
    const int lane = tid & 31;
    const int bm   = blockIdx.y * BM;
    const int bn   = blockIdx.x * BN;
    const int wm   = (warp >> 2) * 64;   // 2 warps along M
    const int wn   = (warp & 3) * 32;    // 4 warps along N
    const int g    = lane >> 2;
    const int tg   = lane & 3;
    const int q    = lane >> 3;          // ldmatrix quad id
    const int li   = lane & 7;

    const uint32_t smem0 = (uint32_t)__cvta_generic_to_shared(dyn);

    const unsigned char* gA = g_Aaug + (size_t)blockIdx.y * NK * A_TILE_BYTES;
    const unsigned char* gB = g_Waug + (size_t)blockIdx.x * NK * B_TILE_BYTES;

    // A frag geometry: mat0 rows m..m+7 @k, mat1 m+8..15 @k, mat2/3 same @k+8
    const int rowA = wm + (q & 1) * 8 + li;
    const uint32_t colA = (uint32_t)((q >> 1) * 16);
    const uint32_t XA = (uint32_t)((rowA & 7) << 4);
    // B frag pair (nt,nt+1): mat0 rows n..n+7 @k, mat1 @k+8, mat2/3 rows n+8..15
    const int rowB = wn + (q >> 1) * 8 + li;
    const uint32_t colB = (uint32_t)((q & 1) * 16);
    const uint32_t XB = (uint32_t)((rowB & 7) << 4);

    float acc[4][4][4];
#pragma unroll
    for (int mt = 0; mt < 4; mt++)
#pragma unroll
        for (int nt = 0; nt < 4; nt++)
#pragma unroll
            for (int r = 0; r < 4; r++) acc[mt][nt][r] = 0.f;

    auto load_stage = [&](int s, int kt) {
        uint32_t As = smem0 + s * STAGE_BYTES;
        uint32_t Bs = As + A_TILE_BYTES;
        const unsigned char* At = gA + (size_t)kt * A_TILE_BYTES;
        const unsigned char* Bt = gB + (size_t)kt * B_TILE_BYTES;
#pragma unroll
        for (int i = 0; i < 4; i++) {          // A: 1024 x 16B
            int c = tid + i * 256;
            cp_async16(As + c * 16, At + c * 16);
        }
#pragma unroll
        for (int i = 0; i < 4; i++) {          // B: 1024 x 16B
            int c = tid + i * 256;
            cp_async16(Bs + c * 16, Bt + c * 16);
        }
    };

    load_stage(0, 0); CP_COMMIT();
    load_stage(1, 1); CP_COMMIT();

    int s = 0;
    for (int kt = 0; kt < NK; kt++) {
        CP_WAIT1();
        __syncthreads();

        const uint32_t As = smem0 + s * STAGE_BYTES;
        const uint32_t Bs = As + A_TILE_BYTES;

#pragma unroll
        for (int ks = 0; ks < 4; ks++) {
            const uint32_t kb = (uint32_t)(ks * 32);
            unsigned af[4][4];
            unsigned bf[4][2];
#pragma unroll
            for (int mt = 0; mt < 4; mt++)
                ldsm_x4(af[mt][0], af[mt][1], af[mt][2], af[mt][3],
                        As + (uint32_t)((rowA + mt * 16) << 7) + ((kb + colA) ^ XA));
#pragma unroll
            for (int np = 0; np < 2; np++)
                ldsm_x4(bf[np * 2][0], bf[np * 2][1], bf[np * 2 + 1][0], bf[np * 2 + 1][1],
                        Bs + (uint32_t)((rowB + np * 16) << 7) + ((kb + colB) ^ XB));
#pragma unroll
            for (int mt = 0; mt < 4; mt++)
#pragma unroll
                for (int nt = 0; nt < 4; nt++)
                    mma_f16(acc[mt][nt], af[mt], bf[nt]);
        }

        if (kt + 2 < NK) load_stage((kt + 2) % STAGES, kt + 2);
        CP_COMMIT();
        s = (s + 1 == STAGES) ? 0 : s + 1;
    }

    // epilogue
#pragma unroll
    for (int mt = 0; mt < 4; mt++) {
#pragma unroll
        for (int nt = 0; nt < 4; nt++) {
            int m0 = bm + wm + mt * 16 + g;
            int n0 = bn + wn + nt * 8 + tg * 2;
            float bs0 = __ldg(&bias[n0]);
            float bs1 = __ldg(&bias[n0 + 1]);
            float2 v0 = make_float2(acc[mt][nt][0] + bs0, acc[mt][nt][1] + bs1);
            float2 v1 = make_float2(acc[mt][nt][2] + bs0, acc[mt][nt][3] + bs1);
            *reinterpret_cast<float2*>(&C[(size_t)m0 * N_DIM + n0]) = v0;
            *reinterpret_cast<float2*>(&C[(size_t)(m0 + 8) * N_DIM + n0]) = v1;
        }
    }
}

// ---------------------------------------------------------------------------
// Launch
// ---------------------------------------------------------------------------
extern "C" void kernel_launch(void* const* d_in, const int* in_sizes, int n_in,
                              void* d_out, int out_size) {
    const float* x      = (const float*)d_in[0];
    const float* coeff  = (const float*)d_in[1];
    const float* w_base = (const float*)d_in[2];
    const float* bias   = (const float*)d_in[3];
    float* out = (float*)d_out;

    cudaFuncSetAttribute(gemm_kernel,
                         cudaFuncAttributeMaxDynamicSharedMemorySize, DYN_BYTES);

    pack_kernel<<<PACK_A_BLOCKS + PACK_W_BLOCKS, 256>>>(x, coeff, w_base);
    gemm_kernel<<<dim3(N_DIM / BN, M_DIM / BM), 256, DYN_BYTES>>>(bias, out);
}